// round 1
// baseline (speedup 1.0000x reference)
#include <cuda_runtime.h>
#include <math.h>

// Problem constants
static constexpr int B_ = 8;
static constexpr int K_ = 2048;   // time / projection dim
static constexpr int D_ = 1024;   // channel dim
static constexpr int CHUNKS = 16; // time chunks for parallel scan
static constexpr int T_ = K_ / CHUNKS; // 128 steps per chunk

// Scratch (no cudaMalloc allowed)
__device__ float g_lam[(size_t)B_ * K_ * D_];            // 64 MB
__device__ float g_A[(size_t)B_ * CHUNKS * D_];          // chunk products
__device__ float g_U[(size_t)B_ * CHUNKS * D_];          // chunk offsets
__device__ float g_carry[(size_t)B_ * CHUNKS * D_];      // carry-in per chunk

// ---------------------------------------------------------------------------
// Kernel 1: batched SGEMM  lam[b,t,d] = sigmoid( sum_k W[t,k] * x[b,k,d] + bias[t] )
//   A = W  [M=2048 x K=2048]  row-major
//   Bmat = x[b] [K=2048 x N=1024] row-major
// Block tile 128x128, BK=8, 256 threads, 8x8 per thread.
// ---------------------------------------------------------------------------
#define BM 128
#define BN 128
#define BKD 8
#define TM 8
#define TN 8

__global__ __launch_bounds__(256, 2)
void gemm_sigmoid_kernel(const float* __restrict__ x,
                         const float* __restrict__ W,
                         const float* __restrict__ bias)
{
    const int bCol = blockIdx.x * BN;       // d tile
    const int bRow = blockIdx.y * BM;       // t tile
    const int batch = blockIdx.z;

    const float* A = W;                                        // [K_ x K_]
    const float* Bm = x + (size_t)batch * K_ * D_;             // [K_ x D_]
    float* C = g_lam + (size_t)batch * K_ * D_;

    __shared__ float As[BKD][BM];
    __shared__ float Bs[BKD][BN];

    const int tid = threadIdx.x;            // 0..255

    // A-tile load mapping: 128 rows x 8 cols = 256 float4 (along k)
    const int aRow = tid >> 1;              // 0..127
    const int aCol = (tid & 1) * 4;         // 0 or 4
    // B-tile load mapping: 8 rows x 128 cols = 256 float4 (along n)
    const int bRowL = tid >> 5;             // 0..7
    const int bColL = (tid & 31) * 4;       // 0..124

    const int tRow = (tid >> 4) * TM;       // 0..120
    const int tCol = (tid & 15) * TN;       // 0..120

    float acc[TM][TN];
    #pragma unroll
    for (int i = 0; i < TM; i++)
        #pragma unroll
        for (int j = 0; j < TN; j++) acc[i][j] = 0.0f;

    for (int k0 = 0; k0 < K_; k0 += BKD) {
        // Load A tile (transpose into As[k][m])
        float4 a4 = *reinterpret_cast<const float4*>(
            &A[(size_t)(bRow + aRow) * K_ + (k0 + aCol)]);
        As[aCol + 0][aRow] = a4.x;
        As[aCol + 1][aRow] = a4.y;
        As[aCol + 2][aRow] = a4.z;
        As[aCol + 3][aRow] = a4.w;
        // Load B tile
        float4 b4 = *reinterpret_cast<const float4*>(
            &Bm[(size_t)(k0 + bRowL) * D_ + (bCol + bColL)]);
        *reinterpret_cast<float4*>(&Bs[bRowL][bColL]) = b4;
        __syncthreads();

        #pragma unroll
        for (int kk = 0; kk < BKD; kk++) {
            float ra[TM], rb[TN];
            // vectorized shared loads (16B aligned: tRow/tCol multiples of 8)
            float4 ra0 = *reinterpret_cast<const float4*>(&As[kk][tRow]);
            float4 ra1 = *reinterpret_cast<const float4*>(&As[kk][tRow + 4]);
            ra[0]=ra0.x; ra[1]=ra0.y; ra[2]=ra0.z; ra[3]=ra0.w;
            ra[4]=ra1.x; ra[5]=ra1.y; ra[6]=ra1.z; ra[7]=ra1.w;
            float4 rb0 = *reinterpret_cast<const float4*>(&Bs[kk][tCol]);
            float4 rb1 = *reinterpret_cast<const float4*>(&Bs[kk][tCol + 4]);
            rb[0]=rb0.x; rb[1]=rb0.y; rb[2]=rb0.z; rb[3]=rb0.w;
            rb[4]=rb1.x; rb[5]=rb1.y; rb[6]=rb1.z; rb[7]=rb1.w;
            #pragma unroll
            for (int i = 0; i < TM; i++)
                #pragma unroll
                for (int j = 0; j < TN; j++)
                    acc[i][j] = fmaf(ra[i], rb[j], acc[i][j]);
        }
        __syncthreads();
    }

    // Epilogue: bias + sigmoid, write lam
    #pragma unroll
    for (int i = 0; i < TM; i++) {
        const float bz = bias[bRow + tRow + i];
        float* crow = &C[(size_t)(bRow + tRow + i) * D_ + (bCol + tCol)];
        #pragma unroll
        for (int j = 0; j < TN; j++) {
            float z = acc[i][j] + bz;
            crow[j] = 1.0f / (1.0f + __expf(-z));
        }
    }
}

// ---------------------------------------------------------------------------
// Scan pass 1: per (b, chunk, d) compute affine summary of the chunk:
//   s_out = A * s_in + U   where A = prod(lam), U = scan value with s_in = 0
// ---------------------------------------------------------------------------
__global__ void scan_pass1(const float* __restrict__ x)
{
    const int tid = blockIdx.x * blockDim.x + threadIdx.x;  // B*CHUNKS*D
    const int d = tid % D_;
    const int c = (tid / D_) % CHUNKS;
    const int b = tid / (D_ * CHUNKS);

    const size_t base = ((size_t)b * K_ + (size_t)c * T_) * D_ + d;
    float A = 1.0f, U = 0.0f;
    #pragma unroll 4
    for (int t = 0; t < T_; t++) {
        const float l  = g_lam[base + (size_t)t * D_];
        const float xv = x[base + (size_t)t * D_];
        U = fmaf(l, U - xv, xv);   // l*U + (1-l)*x
        A *= l;
    }
    const size_t idx = ((size_t)(b * CHUNKS + c)) * D_ + d;  // [b,c,d] layout
    g_A[idx] = A;
    g_U[idx] = U;
}

// ---------------------------------------------------------------------------
// Scan pass 2: per (b, d) scan the CHUNKS chunk summaries, emit carry-in.
// ---------------------------------------------------------------------------
__global__ void scan_pass2()
{
    const int tid = blockIdx.x * blockDim.x + threadIdx.x;  // B*D
    const int d = tid % D_;
    const int b = tid / D_;
    float s = 0.0f;
    #pragma unroll
    for (int c = 0; c < CHUNKS; c++) {
        const size_t idx = ((size_t)(b * CHUNKS + c)) * D_ + d;
        g_carry[idx] = s;
        s = fmaf(g_A[idx], s, g_U[idx]);
    }
}

// ---------------------------------------------------------------------------
// Scan pass 3: re-run each chunk with the correct carry-in, write outputs.
// ---------------------------------------------------------------------------
__global__ void scan_pass3(const float* __restrict__ x, float* __restrict__ ys)
{
    const int tid = blockIdx.x * blockDim.x + threadIdx.x;  // B*CHUNKS*D
    const int d = tid % D_;
    const int c = (tid / D_) % CHUNKS;
    const int b = tid / (D_ * CHUNKS);

    float s = g_carry[((size_t)(b * CHUNKS + c)) * D_ + d];
    const size_t base = ((size_t)b * K_ + (size_t)c * T_) * D_ + d;
    #pragma unroll 4
    for (int t = 0; t < T_; t++) {
        const float l  = g_lam[base + (size_t)t * D_];
        const float xv = x[base + (size_t)t * D_];
        s = fmaf(l, s - xv, xv);   // l*s + (1-l)*x
        ys[base + (size_t)t * D_] = s;
    }
}

// ---------------------------------------------------------------------------
extern "C" void kernel_launch(void* const* d_in, const int* in_sizes, int n_in,
                              void* d_out, int out_size)
{
    const float* x    = (const float*)d_in[0];  // [B, K, D]
    const float* W    = (const float*)d_in[1];  // [K, K]
    const float* bias = (const float*)d_in[2];  // [K]
    float* ys = (float*)d_out;                  // [B, K, D]

    // GEMM + sigmoid -> g_lam
    {
        dim3 grid(D_ / BN, K_ / BM, B_);   // (8, 16, 8)
        gemm_sigmoid_kernel<<<grid, 256>>>(x, W, bias);
    }
    // Chunked parallel scan
    {
        const int total1 = B_ * CHUNKS * D_;            // 131072
        scan_pass1<<<total1 / 256, 256>>>(x);
        const int total2 = B_ * D_;                     // 8192
        scan_pass2<<<total2 / 256, 256>>>();
        scan_pass3<<<total1 / 256, 256>>>(x, ys);
    }
}

// round 3
// speedup vs baseline: 2.3296x; 2.3296x over previous
#include <cuda_runtime.h>
#include <cuda_bf16.h>
#include <cstdint>
#include <math.h>

// ---------------------------------------------------------------------------
// Problem constants
// ---------------------------------------------------------------------------
static constexpr int B_ = 8;
static constexpr int K_ = 2048;   // time / contraction dim
static constexpr int D_ = 1024;   // channel dim
static constexpr int CHUNKS = 16; // time chunks for parallel scan
static constexpr int T_ = K_ / CHUNKS;  // 128

// GEMM tiling: C[t, d] = sum_k W[t,k] * x[k,d]   per batch
static constexpr int BM = 128;   // t tile
static constexpr int BN = 128;   // d tile
static constexpr int BK = 32;    // k per stage
static constexpr int NSTAGE_IT = K_ / BK;  // 64

// smem strides (bytes), padded for conflict-free ldmatrix
static constexpr int W_STRIDE = 80;    // 32 bf16 = 64B + 16B pad
static constexpr int X_STRIDE = 272;   // 128 bf16 = 256B + 16B pad
static constexpr int W_TILE_B = BM * W_STRIDE;        // 10240
static constexpr int X_TILE_B = BK * X_STRIDE;        // 8704
static constexpr int STAGE_B = 2 * W_TILE_B + 2 * X_TILE_B;  // 37888
static constexpr int SMEM_TOTAL = 2 * STAGE_B;               // 75776

// ---------------------------------------------------------------------------
// Device scratch (no cudaMalloc allowed)
// ---------------------------------------------------------------------------
__device__ __align__(256) __nv_bfloat16 g_Whi[(size_t)K_ * K_];
__device__ __align__(256) __nv_bfloat16 g_Wlo[(size_t)K_ * K_];
__device__ __align__(256) __nv_bfloat16 g_xhi[(size_t)B_ * K_ * D_];
__device__ __align__(256) __nv_bfloat16 g_xlo[(size_t)B_ * K_ * D_];
__device__ __align__(256) float g_lam[(size_t)B_ * K_ * D_];
__device__ __align__(256) float g_A[(size_t)B_ * CHUNKS * D_];
__device__ __align__(256) float g_U[(size_t)B_ * CHUNKS * D_];
__device__ __align__(256) float g_carry[(size_t)B_ * CHUNKS * D_];

// ---------------------------------------------------------------------------
// PTX helpers (baseline ISA only: sm_80-class, safe on target sm_103)
// ---------------------------------------------------------------------------
__device__ __forceinline__ uint32_t smem_u32(const void* p) {
    uint32_t a;
    asm("{ .reg .u64 t; cvta.to.shared.u64 t, %1; cvt.u32.u64 %0, t; }"
        : "=r"(a) : "l"(p));
    return a;
}

__device__ __forceinline__ void cp_async16(uint32_t dst, const void* src) {
    asm volatile("cp.async.cg.shared.global [%0], [%1], 16;"
                 :: "r"(dst), "l"(src));
}

__device__ __forceinline__ void ldm_x4(uint32_t* r, uint32_t addr) {
    asm volatile("ldmatrix.sync.aligned.m8n8.x4.shared.b16 {%0,%1,%2,%3}, [%4];"
                 : "=r"(r[0]), "=r"(r[1]), "=r"(r[2]), "=r"(r[3]) : "r"(addr));
}

__device__ __forceinline__ void ldm_x4_t(uint32_t* r, uint32_t addr) {
    asm volatile("ldmatrix.sync.aligned.m8n8.x4.trans.shared.b16 {%0,%1,%2,%3}, [%4];"
                 : "=r"(r[0]), "=r"(r[1]), "=r"(r[2]), "=r"(r[3]) : "r"(addr));
}

__device__ __forceinline__ void mma_bf16(float* c, const uint32_t* a,
                                         const uint32_t b0, const uint32_t b1) {
    asm volatile(
        "mma.sync.aligned.m16n8k16.row.col.f32.bf16.bf16.f32 "
        "{%0,%1,%2,%3}, {%4,%5,%6,%7}, {%8,%9}, {%0,%1,%2,%3};"
        : "+f"(c[0]), "+f"(c[1]), "+f"(c[2]), "+f"(c[3])
        : "r"(a[0]), "r"(a[1]), "r"(a[2]), "r"(a[3]), "r"(b0), "r"(b1));
}

// ---------------------------------------------------------------------------
// Convert W fp32 -> bf16 hi/lo
// ---------------------------------------------------------------------------
__global__ void convert_W_kernel(const float* __restrict__ W) {
    const size_t i = ((size_t)blockIdx.x * blockDim.x + threadIdx.x) * 4;
    float4 v = *reinterpret_cast<const float4*>(W + i);
    __nv_bfloat16 h[4], l[4];
    h[0] = __float2bfloat16(v.x); l[0] = __float2bfloat16(v.x - __bfloat162float(h[0]));
    h[1] = __float2bfloat16(v.y); l[1] = __float2bfloat16(v.y - __bfloat162float(h[1]));
    h[2] = __float2bfloat16(v.z); l[2] = __float2bfloat16(v.z - __bfloat162float(h[2]));
    h[3] = __float2bfloat16(v.w); l[3] = __float2bfloat16(v.w - __bfloat162float(h[3]));
    *reinterpret_cast<uint2*>(g_Whi + i) = *reinterpret_cast<uint2*>(h);
    *reinterpret_cast<uint2*>(g_Wlo + i) = *reinterpret_cast<uint2*>(l);
}

// Convert x fp32 -> bf16 hi/lo (same layout, no transpose)
__global__ void convert_x_kernel(const float* __restrict__ x) {
    const size_t i = ((size_t)blockIdx.x * blockDim.x + threadIdx.x) * 4;
    float4 v = *reinterpret_cast<const float4*>(x + i);
    __nv_bfloat16 h[4], l[4];
    h[0] = __float2bfloat16(v.x); l[0] = __float2bfloat16(v.x - __bfloat162float(h[0]));
    h[1] = __float2bfloat16(v.y); l[1] = __float2bfloat16(v.y - __bfloat162float(h[1]));
    h[2] = __float2bfloat16(v.z); l[2] = __float2bfloat16(v.z - __bfloat162float(h[2]));
    h[3] = __float2bfloat16(v.w); l[3] = __float2bfloat16(v.w - __bfloat162float(h[3]));
    *reinterpret_cast<uint2*>(g_xhi + i) = *reinterpret_cast<uint2*>(h);
    *reinterpret_cast<uint2*>(g_xlo + i) = *reinterpret_cast<uint2*>(l);
}

// ---------------------------------------------------------------------------
// GEMM: lam[b,t,d] = sigmoid( sum_k W[t,k]*x[b,k,d] + bias[t] )
// Split bf16, 3 mma.sync terms. 256 threads, 8 warps (2x4), each 64x32.
// ---------------------------------------------------------------------------
__device__ __forceinline__ void load_stage(uint32_t sbase,
                                           const __nv_bfloat16* Wh,
                                           const __nv_bfloat16* Wl,
                                           const __nv_bfloat16* xh,
                                           const __nv_bfloat16* xl,
                                           int k0, int tid) {
    // W tiles: 128 rows x 4 segs of 16B
    #pragma unroll
    for (int u = tid; u < 512; u += 256) {
        const int row = u >> 2, seg = u & 3;
        const uint32_t off = (uint32_t)(row * W_STRIDE + seg * 16);
        const __nv_bfloat16* gh = Wh + (size_t)row * K_ + k0 + seg * 8;
        const __nv_bfloat16* gl = Wl + (size_t)row * K_ + k0 + seg * 8;
        cp_async16(sbase + off, gh);
        cp_async16(sbase + W_TILE_B + off, gl);
    }
    // x tiles: 32 rows x 16 segs of 16B
    #pragma unroll
    for (int u = tid; u < 512; u += 256) {
        const int row = u >> 4, seg = u & 15;
        const uint32_t off = (uint32_t)(row * X_STRIDE + seg * 16);
        const __nv_bfloat16* gh = xh + (size_t)(k0 + row) * D_ + seg * 8;
        const __nv_bfloat16* gl = xl + (size_t)(k0 + row) * D_ + seg * 8;
        cp_async16(sbase + 2 * W_TILE_B + off, gh);
        cp_async16(sbase + 2 * W_TILE_B + X_TILE_B + off, gl);
    }
    asm volatile("cp.async.commit_group;" ::: "memory");
}

__global__ __launch_bounds__(256, 1)
void gemm_sigmoid_kernel(const float* __restrict__ bias) {
    extern __shared__ char smem[];
    const uint32_t sb = smem_u32(smem);
    const int tid = threadIdx.x;
    const int lane = tid & 31;
    const int warp = tid >> 5;
    const int wm = warp >> 2;          // 0..1  (64 rows each)
    const int wn = warp & 3;           // 0..3  (32 cols each)

    const int d0 = blockIdx.x * BN;
    const int t0 = blockIdx.y * BM;
    const int b = blockIdx.z;

    const __nv_bfloat16* Wh = g_Whi + (size_t)t0 * K_;
    const __nv_bfloat16* Wl = g_Wlo + (size_t)t0 * K_;
    const __nv_bfloat16* xh = g_xhi + (size_t)b * K_ * D_ + d0;
    const __nv_bfloat16* xl = g_xlo + (size_t)b * K_ * D_ + d0;

    float acc[4][4][4];
    #pragma unroll
    for (int i = 0; i < 4; i++)
        #pragma unroll
        for (int j = 0; j < 4; j++)
            #pragma unroll
            for (int q = 0; q < 4; q++) acc[i][j][q] = 0.0f;

    // ldmatrix base offsets (per lane)
    const int a_row_in = (lane & 15);        // row within 16
    const int a_kseg = (lane >> 4);          // 0/1 -> k offset 0/8
    const int b_krow = (lane & 15);          // k row within 16
    const int b_nseg = (lane >> 4);          // 0/1 -> n offset 0/8

    load_stage(sb, Wh, Wl, xh, xl, 0, tid);

    for (int c = 0; c < NSTAGE_IT; c++) {
        asm volatile("cp.async.wait_group 0;" ::: "memory");
        __syncthreads();
        if (c + 1 < NSTAGE_IT)
            load_stage(sb + ((c + 1) & 1) * STAGE_B, Wh, Wl, xh, xl,
                       (c + 1) * BK, tid);

        const uint32_t st = sb + (c & 1) * STAGE_B;
        const uint32_t sWh = st;
        const uint32_t sWl = st + W_TILE_B;
        const uint32_t sXh = st + 2 * W_TILE_B;
        const uint32_t sXl = st + 2 * W_TILE_B + X_TILE_B;

        #pragma unroll
        for (int kk = 0; kk < 2; kk++) {  // two k16 steps
            uint32_t ahi[4][4], alo[4][4];
            #pragma unroll
            for (int i = 0; i < 4; i++) {
                const uint32_t aoff =
                    (uint32_t)((wm * 64 + i * 16 + a_row_in) * W_STRIDE +
                               kk * 32 + a_kseg * 16);
                ldm_x4(ahi[i], sWh + aoff);
                ldm_x4(alo[i], sWl + aoff);
            }
            uint32_t bhi[2][4], blo[2][4];
            #pragma unroll
            for (int j = 0; j < 2; j++) {
                const uint32_t boff =
                    (uint32_t)((kk * 16 + b_krow) * X_STRIDE +
                               (wn * 32 + j * 16 + b_nseg * 8) * 2);
                ldm_x4_t(bhi[j], sXh + boff);
                ldm_x4_t(blo[j], sXl + boff);
            }
            #pragma unroll
            for (int i = 0; i < 4; i++) {
                #pragma unroll
                for (int j2 = 0; j2 < 4; j2++) {
                    const int jp = j2 >> 1, h = (j2 & 1) * 2;
                    mma_bf16(acc[i][j2], ahi[i], bhi[jp][h], bhi[jp][h + 1]);
                    mma_bf16(acc[i][j2], ahi[i], blo[jp][h], blo[jp][h + 1]);
                    mma_bf16(acc[i][j2], alo[i], bhi[jp][h], bhi[jp][h + 1]);
                }
            }
        }
        __syncthreads();
    }

    // Epilogue: bias + sigmoid -> g_lam[b,t,d]
    const int gr = lane >> 2;
    const int gc = (lane & 3) * 2;
    float* lamB = g_lam + (size_t)b * K_ * D_;
    #pragma unroll
    for (int i = 0; i < 4; i++) {
        const int trow0 = t0 + wm * 64 + i * 16 + gr;
        const float bz0 = __ldg(&bias[trow0]);
        const float bz1 = __ldg(&bias[trow0 + 8]);
        #pragma unroll
        for (int j2 = 0; j2 < 4; j2++) {
            const int dcol = d0 + wn * 32 + j2 * 8 + gc;
            float2 v0, v1;
            v0.x = 1.0f / (1.0f + __expf(-(acc[i][j2][0] + bz0)));
            v0.y = 1.0f / (1.0f + __expf(-(acc[i][j2][1] + bz0)));
            v1.x = 1.0f / (1.0f + __expf(-(acc[i][j2][2] + bz1)));
            v1.y = 1.0f / (1.0f + __expf(-(acc[i][j2][3] + bz1)));
            *reinterpret_cast<float2*>(&lamB[(size_t)trow0 * D_ + dcol]) = v0;
            *reinterpret_cast<float2*>(&lamB[(size_t)(trow0 + 8) * D_ + dcol]) = v1;
        }
    }
}

// ---------------------------------------------------------------------------
// Scan pass 1: per (b, chunk, d) affine summary of the chunk
// ---------------------------------------------------------------------------
__global__ void scan_pass1(const float* __restrict__ x) {
    const int g = blockIdx.x * blockDim.x + threadIdx.x;
    const int d = g % D_;
    const int c = (g / D_) % CHUNKS;
    const int b = g / (D_ * CHUNKS);

    const size_t base = ((size_t)b * K_ + (size_t)c * T_) * D_ + d;
    float A = 1.0f, U = 0.0f;
    #pragma unroll 4
    for (int t = 0; t < T_; t++) {
        const float l = g_lam[base + (size_t)t * D_];
        const float xv = x[base + (size_t)t * D_];
        U = fmaf(l, U - xv, xv);
        A *= l;
    }
    const size_t idx = ((size_t)(b * CHUNKS + c)) * D_ + d;
    g_A[idx] = A;
    g_U[idx] = U;
}

__global__ void scan_pass2() {
    const int g = blockIdx.x * blockDim.x + threadIdx.x;  // B*D
    const int d = g % D_;
    const int b = g / D_;
    float s = 0.0f;
    #pragma unroll
    for (int c = 0; c < CHUNKS; c++) {
        const size_t idx = ((size_t)(b * CHUNKS + c)) * D_ + d;
        g_carry[idx] = s;
        s = fmaf(g_A[idx], s, g_U[idx]);
    }
}

__global__ void scan_pass3(const float* __restrict__ x, float* __restrict__ ys) {
    const int g = blockIdx.x * blockDim.x + threadIdx.x;
    const int d = g % D_;
    const int c = (g / D_) % CHUNKS;
    const int b = g / (D_ * CHUNKS);

    float s = g_carry[((size_t)(b * CHUNKS + c)) * D_ + d];
    const size_t base = ((size_t)b * K_ + (size_t)c * T_) * D_ + d;
    #pragma unroll 4
    for (int t = 0; t < T_; t++) {
        const float l = g_lam[base + (size_t)t * D_];
        const float xv = x[base + (size_t)t * D_];
        s = fmaf(l, s - xv, xv);
        ys[base + (size_t)t * D_] = s;
    }
}

// ---------------------------------------------------------------------------
extern "C" void kernel_launch(void* const* d_in, const int* in_sizes, int n_in,
                              void* d_out, int out_size) {
    const float* x    = (const float*)d_in[0];  // [B, K, D]
    const float* W    = (const float*)d_in[1];  // [K, K]
    const float* bias = (const float*)d_in[2];  // [K]
    float* ys = (float*)d_out;                  // [B, K, D]

    static bool attr_set = false;
    if (!attr_set) {
        cudaFuncSetAttribute(gemm_sigmoid_kernel,
                             cudaFuncAttributeMaxDynamicSharedMemorySize,
                             SMEM_TOTAL);
        attr_set = true;
    }

    convert_W_kernel<<<(K_ * K_) / (256 * 4), 256>>>(W);
    convert_x_kernel<<<((size_t)B_ * K_ * D_) / (256 * 4), 256>>>(x);

    gemm_sigmoid_kernel<<<dim3(D_ / BN, K_ / BM, B_), 256, SMEM_TOTAL>>>(bias);

    scan_pass1<<<(B_ * CHUNKS * D_) / 256, 256>>>(x);
    scan_pass2<<<(B_ * D_) / 256, 256>>>();
    scan_pass3<<<(B_ * CHUNKS * D_) / 256, 256>>>(x, ys);
}